// round 2
// baseline (speedup 1.0000x reference)
#include <cuda_runtime.h>
#include <cuda_bf16.h>
#include <cstdint>

// ---------------------------------------------------------------------------
// Problem constants
// ---------------------------------------------------------------------------
#define D_IN   4096
#define D_OUT  4096
#define M_TOT  8192
#define RANK   64

// GEMM tiling
#define TM 128
#define TN 128
#define TK 32
#define STAGES 4
#define K_ITERS (D_IN / TK)         // 128
#define M_TILES (M_TOT / TM)        // 64
#define N_TILES (D_OUT / TN)        // 32

#define PAD 4
#define ROWF (TK + PAD)             // 36 floats per smem row
#define A_STAGE_F (TM * ROWF)       // 4608 floats
#define B_STAGE_F (TN * ROWF)
#define SMEM_FLOATS (STAGES * (A_STAGE_F + B_STAGE_F))
#define SMEM_BYTES  (SMEM_FLOATS * 4)   // 147456

// ---------------------------------------------------------------------------
// Device globals (allocation-free scratch)
// ---------------------------------------------------------------------------
__constant__ float c_nf4[16] = {
    -1.0f, -0.6962f, -0.5251f, -0.3949f, -0.2844f, -0.1848f,
    -0.0911f, 0.0f, 0.0796f, 0.1609f, 0.2461f, 0.3379f,
    0.4407f, 0.5626f, 0.723f, 1.0f};

__device__ __align__(1024) float g_weff[(size_t)D_OUT * D_IN];  // dequant + folded LoRA, tf32
__device__ __align__(1024) float g_xr[(size_t)M_TOT * D_IN];    // x rounded to nearest tf32

// ---------------------------------------------------------------------------
// Helpers
// ---------------------------------------------------------------------------
__device__ __forceinline__ float round_tf32(float v) {
    uint32_t b;
    asm("cvt.rna.tf32.f32 %0, %1;" : "=r"(b) : "f"(v));
    return __uint_as_float(b);
}

__device__ __forceinline__ void cp_async16(uint32_t smem_addr, const void* gptr) {
    asm volatile("cp.async.cg.shared.global [%0], [%1], 16;"
                 :: "r"(smem_addr), "l"(gptr) : "memory");
}
#define CP_COMMIT() asm volatile("cp.async.commit_group;" ::: "memory")
#define CP_WAIT(n)  asm volatile("cp.async.wait_group %0;" :: "n"(n) : "memory")

__device__ __forceinline__ void mma_tf32(float* c, const uint32_t* a, const uint32_t* b) {
    asm volatile(
        "mma.sync.aligned.m16n8k8.row.col.f32.tf32.tf32.f32 "
        "{%0,%1,%2,%3}, {%4,%5,%6,%7}, {%8,%9}, {%0,%1,%2,%3};"
        : "+f"(c[0]), "+f"(c[1]), "+f"(c[2]), "+f"(c[3])
        : "r"(a[0]), "r"(a[1]), "r"(a[2]), "r"(a[3]), "r"(b[0]), "r"(b[1]));
}

// ---------------------------------------------------------------------------
// Prep 1: round x to nearest tf32
// ---------------------------------------------------------------------------
__global__ __launch_bounds__(256) void round_x_kernel(const float4* __restrict__ x,
                                                      float4* __restrict__ xr, int n4) {
    int i = blockIdx.x * blockDim.x + threadIdx.x;
    int stride = gridDim.x * blockDim.x;
    for (; i < n4; i += stride) {
        float4 v = x[i];
        v.x = round_tf32(v.x);
        v.y = round_tf32(v.y);
        v.z = round_tf32(v.z);
        v.w = round_tf32(v.w);
        xr[i] = v;
    }
}

// ---------------------------------------------------------------------------
// Prep 2: W_eff[o,i] = NF4[q[o,i]]*scale + 0.25 * (B@A)[o,i], tf32-rounded
// ---------------------------------------------------------------------------
__global__ __launch_bounds__(256) void prep_weff_kernel(
    const int* __restrict__ q, const float* __restrict__ wscale,
    const float* __restrict__ lA, const float* __restrict__ lB,
    float* __restrict__ weff) {
    __shared__ float sA[64][68];
    __shared__ float sB[64][68];
    const int tid = threadIdx.x;
    const int i0 = blockIdx.x * 64;
    const int o0 = blockIdx.y * 64;

    for (int idx = tid; idx < 64 * 64; idx += 256) {
        int r = idx >> 6, c = idx & 63;
        sA[r][c] = lA[r * D_IN + i0 + c];
    }
    for (int idx = tid; idx < 64 * 64; idx += 256) {
        int o = idx >> 6, r = idx & 63;
        sB[r][o] = lB[(size_t)(o0 + o) * RANK + r];
    }
    __syncthreads();

    const int tx = tid & 15;
    const int ty = tid >> 4;
    float acc[4][4] = {};
#pragma unroll
    for (int r = 0; r < 64; r++) {
        const float4 av = *reinterpret_cast<const float4*>(&sA[r][tx * 4]);
        const float4 bv = *reinterpret_cast<const float4*>(&sB[r][ty * 4]);
        const float a[4] = {av.x, av.y, av.z, av.w};
        const float b[4] = {bv.x, bv.y, bv.z, bv.w};
#pragma unroll
        for (int ii = 0; ii < 4; ii++)
#pragma unroll
            for (int jj = 0; jj < 4; jj++)
                acc[ii][jj] += b[ii] * a[jj];
    }

    const float s = wscale[0];
#pragma unroll
    for (int ii = 0; ii < 4; ii++) {
        const size_t o = o0 + ty * 4 + ii;
        const int4 qv = *reinterpret_cast<const int4*>(&q[o * D_IN + i0 + tx * 4]);
        float4 outv;
        outv.x = round_tf32(c_nf4[qv.x & 15] * s + 0.25f * acc[ii][0]);
        outv.y = round_tf32(c_nf4[qv.y & 15] * s + 0.25f * acc[ii][1]);
        outv.z = round_tf32(c_nf4[qv.z & 15] * s + 0.25f * acc[ii][2]);
        outv.w = round_tf32(c_nf4[qv.w & 15] * s + 0.25f * acc[ii][3]);
        *reinterpret_cast<float4*>(&weff[o * D_IN + i0 + tx * 4]) = outv;
    }
}

// ---------------------------------------------------------------------------
// Main GEMM: C[m,n] = sum_k Xr[m,k] * Weff[n,k]
// mma.sync.m16n8k8.tf32, 128x128 CTA, 4-stage cp.async pipeline
// ---------------------------------------------------------------------------
__global__ void __launch_bounds__(256, 1)
gemm_tf32_kernel(const float* __restrict__ A, const float* __restrict__ B,
                 float* __restrict__ C) {
    extern __shared__ float smem[];
    float* As = smem;                          // [STAGES][TM][ROWF]
    float* Bs = smem + STAGES * A_STAGE_F;     // [STAGES][TN][ROWF]

    const int tid = threadIdx.x;
    const int warp = tid >> 5;
    const int lane = tid & 31;

    // tile mapping with M-grouping for L2 reuse
    const int bid = blockIdx.x;
    const int GROUP_M = 8;
    const int per_group = GROUP_M * N_TILES;
    const int g = bid / per_group, rem = bid % per_group;
    const int mt = g * GROUP_M + (rem % GROUP_M);
    const int nt = rem / GROUP_M;
    const int m0 = mt * TM, n0 = nt * TN;

    // warp tile: 2 (M) x 4 (N) warps -> 64x32 per warp
    const int wm = (warp & 1) * 64;
    const int wn = (warp >> 1) * 32;

    // load indexing: 1024 float4 per operand per stage; 4 per thread
    const int lrow = tid >> 3;          // 0..31 base row (x4 iters -> 128 rows)
    const int lcol = (tid & 7) * 4;     // float col 0..28

    uint32_t as_base = (uint32_t)__cvta_generic_to_shared(As);
    uint32_t bs_base = (uint32_t)__cvta_generic_to_shared(Bs);

    auto load_stage = [&](int kt, int s) {
        const int k0 = kt * TK;
        const float* ga = A + (size_t)(m0) * D_IN + k0;
        const float* gb = B + (size_t)(n0) * D_IN + k0;
        uint32_t sa = as_base + (s * A_STAGE_F) * 4;
        uint32_t sb = bs_base + (s * B_STAGE_F) * 4;
#pragma unroll
        for (int it = 0; it < 4; it++) {
            int row = lrow + it * 32;
            cp_async16(sa + (row * ROWF + lcol) * 4, ga + (size_t)row * D_IN + lcol);
        }
#pragma unroll
        for (int it = 0; it < 4; it++) {
            int row = lrow + it * 32;
            cp_async16(sb + (row * ROWF + lcol) * 4, gb + (size_t)row * D_IN + lcol);
        }
    };

    // prologue: stages 0..STAGES-2
#pragma unroll
    for (int s = 0; s < STAGES - 1; s++) {
        load_stage(s, s);
        CP_COMMIT();
    }

    float acc[4][4][4];
#pragma unroll
    for (int mi = 0; mi < 4; mi++)
#pragma unroll
        for (int ni = 0; ni < 4; ni++)
#pragma unroll
            for (int c = 0; c < 4; c++) acc[mi][ni][c] = 0.f;

    const int ar = lane >> 2;       // 0..7
    const int ac = lane & 3;        // 0..3

    for (int kt = 0; kt < K_ITERS; kt++) {
        if (kt + STAGES - 1 < K_ITERS) load_stage(kt + STAGES - 1, (kt + STAGES - 1) % STAGES);
        CP_COMMIT();
        CP_WAIT(STAGES - 1);
        __syncthreads();

        const float* As_ = As + (kt % STAGES) * A_STAGE_F;
        const float* Bs_ = Bs + (kt % STAGES) * B_STAGE_F;

#pragma unroll
        for (int kk = 0; kk < 4; kk++) {
            const int k0 = kk * 8;
            uint32_t afr[4][4];
#pragma unroll
            for (int mi = 0; mi < 4; mi++) {
                const int r = wm + mi * 16 + ar;
                afr[mi][0] = __float_as_uint(As_[r * ROWF + k0 + ac]);
                afr[mi][1] = __float_as_uint(As_[(r + 8) * ROWF + k0 + ac]);
                afr[mi][2] = __float_as_uint(As_[r * ROWF + k0 + ac + 4]);
                afr[mi][3] = __float_as_uint(As_[(r + 8) * ROWF + k0 + ac + 4]);
            }
            uint32_t bfr[4][2];
#pragma unroll
            for (int ni = 0; ni < 4; ni++) {
                const int c = wn + ni * 8 + ar;
                bfr[ni][0] = __float_as_uint(Bs_[c * ROWF + k0 + ac]);
                bfr[ni][1] = __float_as_uint(Bs_[c * ROWF + k0 + ac + 4]);
            }
#pragma unroll
            for (int mi = 0; mi < 4; mi++)
#pragma unroll
                for (int ni = 0; ni < 4; ni++)
                    mma_tf32(acc[mi][ni], afr[mi], bfr[ni]);
        }
        __syncthreads();
    }

    // epilogue: STG.64 per accumulator pair
    const int crow = lane >> 2;          // 0..7
    const int ccol = (lane & 3) * 2;     // 0,2,4,6
#pragma unroll
    for (int mi = 0; mi < 4; mi++) {
#pragma unroll
        for (int ni = 0; ni < 4; ni++) {
            const size_t m = (size_t)m0 + wm + mi * 16 + crow;
            const int n = n0 + wn + ni * 8 + ccol;
            float2 v0 = {acc[mi][ni][0], acc[mi][ni][1]};
            float2 v1 = {acc[mi][ni][2], acc[mi][ni][3]};
            *reinterpret_cast<float2*>(C + m * D_OUT + n) = v0;
            *reinterpret_cast<float2*>(C + (m + 8) * D_OUT + n) = v1;
        }
    }
}

// ---------------------------------------------------------------------------
// Host side
// ---------------------------------------------------------------------------
extern "C" void kernel_launch(void* const* d_in, const int* in_sizes, int n_in,
                              void* d_out, int out_size) {
    const float* x  = (const float*)d_in[0];
    const int*   q  = (const int*)d_in[1];
    const float* ws = (const float*)d_in[2];
    const float* lA = (const float*)d_in[3];
    const float* lB = (const float*)d_in[4];
    float* out = (float*)d_out;

    float* weff = nullptr;
    float* xr = nullptr;
    cudaGetSymbolAddress((void**)&weff, g_weff);
    cudaGetSymbolAddress((void**)&xr, g_xr);

    round_x_kernel<<<2048, 256>>>((const float4*)x, (float4*)xr,
                                  (int)((size_t)M_TOT * D_IN / 4));
    dim3 pgrid(D_IN / 64, D_OUT / 64);
    prep_weff_kernel<<<pgrid, 256>>>(q, ws, lA, lB, weff);

    cudaFuncSetAttribute(gemm_tf32_kernel,
                         cudaFuncAttributeMaxDynamicSharedMemorySize, SMEM_BYTES);
    gemm_tf32_kernel<<<M_TILES * N_TILES, 256, SMEM_BYTES>>>(xr, weff, out);
}

// round 3
// speedup vs baseline: 1.8927x; 1.8927x over previous
#include <cuda_runtime.h>
#include <cuda_fp16.h>
#include <cstdint>

// ---------------------------------------------------------------------------
// Problem constants
// ---------------------------------------------------------------------------
#define D_IN   4096
#define D_OUT  4096
#define M_TOT  8192
#define RANK   64

// GEMM tiling (fp16 operands, fp32 accumulate)
#define TM 128
#define TN 128
#define TK 64                        // halves per K-stage = 128 bytes
#define STAGES 4
#define K_ITERS (D_IN / TK)          // 64
#define M_TILES (M_TOT / TM)         // 64
#define N_TILES (D_OUT / TN)         // 32

#define PADH 8
#define ROWH (TK + PADH)             // 72 halves = 144 B rows (odd 16B units -> conflict-free)
#define A_STAGE_H (TM * ROWH)        // 9216 halves = 18432 B
#define B_STAGE_H (TN * ROWH)
#define SMEM_BYTES ((STAGES * (A_STAGE_H + B_STAGE_H)) * 2)   // 147456

// ---------------------------------------------------------------------------
// Device globals (allocation-free scratch)
// ---------------------------------------------------------------------------
__constant__ float c_nf4[16] = {
    -1.0f, -0.6962f, -0.5251f, -0.3949f, -0.2844f, -0.1848f,
    -0.0911f, 0.0f, 0.0796f, 0.1609f, 0.2461f, 0.3379f,
    0.4407f, 0.5626f, 0.723f, 1.0f};

__device__ __align__(1024) __half g_wh[(size_t)D_OUT * D_IN];  // dequant + folded LoRA, fp16
__device__ __align__(1024) __half g_xh[(size_t)M_TOT * D_IN];  // x in fp16

// ---------------------------------------------------------------------------
// Helpers
// ---------------------------------------------------------------------------
__device__ __forceinline__ void cp_async16(uint32_t smem_addr, const void* gptr) {
    asm volatile("cp.async.cg.shared.global [%0], [%1], 16;"
                 :: "r"(smem_addr), "l"(gptr) : "memory");
}
#define CP_COMMIT() asm volatile("cp.async.commit_group;" ::: "memory")
#define CP_WAIT(n)  asm volatile("cp.async.wait_group %0;" :: "n"(n) : "memory")

#define LDMATRIX_X4(r0, r1, r2, r3, addr)                                     \
    asm volatile("ldmatrix.sync.aligned.m8n8.x4.shared.b16 {%0,%1,%2,%3}, [%4];" \
                 : "=r"(r0), "=r"(r1), "=r"(r2), "=r"(r3) : "r"(addr))

__device__ __forceinline__ void mma_f16(float* c, const uint32_t* a, const uint32_t* b) {
    asm volatile(
        "mma.sync.aligned.m16n8k16.row.col.f32.f16.f16.f32 "
        "{%0,%1,%2,%3}, {%4,%5,%6,%7}, {%8,%9}, {%0,%1,%2,%3};"
        : "+f"(c[0]), "+f"(c[1]), "+f"(c[2]), "+f"(c[3])
        : "r"(a[0]), "r"(a[1]), "r"(a[2]), "r"(a[3]), "r"(b[0]), "r"(b[1]));
}

__device__ __forceinline__ uint32_t h2_bits(__half2 h) {
    return *reinterpret_cast<uint32_t*>(&h);
}

// ---------------------------------------------------------------------------
// Prep 1: convert x to fp16
// ---------------------------------------------------------------------------
__global__ __launch_bounds__(256) void convert_x_kernel(const float4* __restrict__ x,
                                                        uint2* __restrict__ xh, int n4) {
    int i = blockIdx.x * blockDim.x + threadIdx.x;
    int stride = gridDim.x * blockDim.x;
    for (; i < n4; i += stride) {
        float4 v = x[i];
        uint2 o;
        o.x = h2_bits(__floats2half2_rn(v.x, v.y));
        o.y = h2_bits(__floats2half2_rn(v.z, v.w));
        xh[i] = o;
    }
}

// ---------------------------------------------------------------------------
// Prep 2: W_eff[o,i] = NF4[q[o,i]]*scale + 0.25 * (B@A)[o,i], to fp16
// ---------------------------------------------------------------------------
__global__ __launch_bounds__(256) void prep_weff_kernel(
    const int* __restrict__ q, const float* __restrict__ wscale,
    const float* __restrict__ lA, const float* __restrict__ lB,
    uint2* __restrict__ wh) {
    __shared__ float sA[64][68];
    __shared__ float sB[64][68];
    const int tid = threadIdx.x;
    const int i0 = blockIdx.x * 64;
    const int o0 = blockIdx.y * 64;

    for (int idx = tid; idx < 64 * 64; idx += 256) {
        int r = idx >> 6, c = idx & 63;
        sA[r][c] = lA[r * D_IN + i0 + c];
    }
    for (int idx = tid; idx < 64 * 64; idx += 256) {
        int o = idx >> 6, r = idx & 63;
        sB[r][o] = lB[(size_t)(o0 + o) * RANK + r];
    }
    __syncthreads();

    const int tx = tid & 15;
    const int ty = tid >> 4;
    float acc[4][4] = {};
#pragma unroll
    for (int r = 0; r < 64; r++) {
        const float4 av = *reinterpret_cast<const float4*>(&sA[r][tx * 4]);
        const float4 bv = *reinterpret_cast<const float4*>(&sB[r][ty * 4]);
        const float a[4] = {av.x, av.y, av.z, av.w};
        const float b[4] = {bv.x, bv.y, bv.z, bv.w};
#pragma unroll
        for (int ii = 0; ii < 4; ii++)
#pragma unroll
            for (int jj = 0; jj < 4; jj++)
                acc[ii][jj] += b[ii] * a[jj];
    }

    const float s = wscale[0];
#pragma unroll
    for (int ii = 0; ii < 4; ii++) {
        const size_t o = o0 + ty * 4 + ii;
        const int4 qv = *reinterpret_cast<const int4*>(&q[o * D_IN + i0 + tx * 4]);
        float f0 = c_nf4[qv.x & 15] * s + 0.25f * acc[ii][0];
        float f1 = c_nf4[qv.y & 15] * s + 0.25f * acc[ii][1];
        float f2 = c_nf4[qv.z & 15] * s + 0.25f * acc[ii][2];
        float f3 = c_nf4[qv.w & 15] * s + 0.25f * acc[ii][3];
        uint2 o2;
        o2.x = h2_bits(__floats2half2_rn(f0, f1));
        o2.y = h2_bits(__floats2half2_rn(f2, f3));
        wh[(o * D_IN + i0 + tx * 4) >> 2] = o2;
    }
}

// ---------------------------------------------------------------------------
// Main GEMM: C[m,n] = sum_k Xh[m,k] * Wh[n,k]
// mma.sync.m16n8k16.f16 + ldmatrix, 128x128 CTA, 4-stage cp.async pipeline
// ---------------------------------------------------------------------------
__global__ void __launch_bounds__(256, 1)
gemm_f16_kernel(const __half* __restrict__ A, const __half* __restrict__ B,
                float* __restrict__ C) {
    extern __shared__ __half smem[];
    __half* As = smem;                            // [STAGES][TM][ROWH]
    __half* Bs = smem + STAGES * A_STAGE_H;       // [STAGES][TN][ROWH]

    const int tid = threadIdx.x;
    const int warp = tid >> 5;
    const int lane = tid & 31;

    // tile mapping with M-grouping for L2 reuse
    const int bid = blockIdx.x;
    const int GROUP_M = 8;
    const int per_group = GROUP_M * N_TILES;
    const int g = bid / per_group, rem = bid % per_group;
    const int mt = g * GROUP_M + (rem % GROUP_M);
    const int nt = rem / GROUP_M;
    const int m0 = mt * TM, n0 = nt * TN;

    // warp tile: 2 (M) x 4 (N) warps -> 64x32 per warp
    const int wm = (warp & 1) * 64;
    const int wn = (warp >> 1) * 32;

    // cp.async indexing: 8 x 16B chunks per 128B row; 8 threads/row
    const int lrow = tid >> 3;                    // 0..31, x4 iters
    const int lcolh = (tid & 7) * 8;              // half col 0..56

    const uint32_t as_base = (uint32_t)__cvta_generic_to_shared(As);
    const uint32_t bs_base = (uint32_t)__cvta_generic_to_shared(Bs);

    auto load_stage = [&](int kt, int s) {
        const int k0 = kt * TK;
        const __half* ga = A + (size_t)m0 * D_IN + k0 + lcolh;
        const __half* gb = B + (size_t)n0 * D_IN + k0 + lcolh;
        uint32_t sa = as_base + (s * A_STAGE_H + lcolh) * 2;
        uint32_t sb = bs_base + (s * B_STAGE_H + lcolh) * 2;
#pragma unroll
        for (int it = 0; it < 4; it++) {
            int row = lrow + it * 32;
            cp_async16(sa + row * (ROWH * 2), ga + (size_t)row * D_IN);
        }
#pragma unroll
        for (int it = 0; it < 4; it++) {
            int row = lrow + it * 32;
            cp_async16(sb + row * (ROWH * 2), gb + (size_t)row * D_IN);
        }
    };

#pragma unroll
    for (int s = 0; s < STAGES - 1; s++) {
        load_stage(s, s);
        CP_COMMIT();
    }

    float acc[4][4][4];
#pragma unroll
    for (int mi = 0; mi < 4; mi++)
#pragma unroll
        for (int ni = 0; ni < 4; ni++)
#pragma unroll
            for (int c = 0; c < 4; c++) acc[mi][ni][c] = 0.f;

    // ldmatrix per-lane addressing
    const int lg = lane >> 3;       // 8x8 tile group 0..3
    const int lr = lane & 7;
    // A x4 tiles: g0=(r0-7,k0) g1=(r8-15,k0) g2=(r0-7,k8) g3=(r8-15,k8)
    const int a_row = lr + (lg & 1) * 8;
    const int a_kof = (lg >> 1) * 8;
    // B x4 tiles: g0=(n0-7,k0) g1=(n0-7,k8) g2=(n8-15,k0) g3=(n8-15,k8)
    const int b_row = lr + (lg >> 1) * 8;
    const int b_kof = (lg & 1) * 8;

    for (int kt = 0; kt < K_ITERS; kt++) {
        if (kt + STAGES - 1 < K_ITERS) load_stage(kt + STAGES - 1, (kt + STAGES - 1) % STAGES);
        CP_COMMIT();
        CP_WAIT(STAGES - 1);
        __syncthreads();

        const int s = kt % STAGES;
        const uint32_t as_st = as_base + (s * A_STAGE_H) * 2;
        const uint32_t bs_st = bs_base + (s * B_STAGE_H) * 2;

#pragma unroll
        for (int kk = 0; kk < 4; kk++) {
            const int k0 = kk * 16;
            uint32_t af[4][4];
#pragma unroll
            for (int mi = 0; mi < 4; mi++) {
                uint32_t addr = as_st + ((wm + mi * 16 + a_row) * ROWH + k0 + a_kof) * 2;
                LDMATRIX_X4(af[mi][0], af[mi][1], af[mi][2], af[mi][3], addr);
            }
            uint32_t bf[2][4];
#pragma unroll
            for (int n2 = 0; n2 < 2; n2++) {
                uint32_t addr = bs_st + ((wn + n2 * 16 + b_row) * ROWH + k0 + b_kof) * 2;
                LDMATRIX_X4(bf[n2][0], bf[n2][1], bf[n2][2], bf[n2][3], addr);
            }
#pragma unroll
            for (int mi = 0; mi < 4; mi++)
#pragma unroll
                for (int n2 = 0; n2 < 2; n2++) {
                    mma_f16(acc[mi][n2 * 2 + 0], af[mi], &bf[n2][0]);
                    mma_f16(acc[mi][n2 * 2 + 1], af[mi], &bf[n2][2]);
                }
        }
        __syncthreads();
    }

    // epilogue: STG.64 per accumulator pair
    const int crow = lane >> 2;
    const int ccol = (lane & 3) * 2;
#pragma unroll
    for (int mi = 0; mi < 4; mi++) {
#pragma unroll
        for (int ni = 0; ni < 4; ni++) {
            const size_t m = (size_t)m0 + wm + mi * 16 + crow;
            const int n = n0 + wn + ni * 8 + ccol;
            float2 v0 = {acc[mi][ni][0], acc[mi][ni][1]};
            float2 v1 = {acc[mi][ni][2], acc[mi][ni][3]};
            *reinterpret_cast<float2*>(C + m * D_OUT + n) = v0;
            *reinterpret_cast<float2*>(C + (m + 8) * D_OUT + n) = v1;
        }
    }
}

// ---------------------------------------------------------------------------
// Host side
// ---------------------------------------------------------------------------
extern "C" void kernel_launch(void* const* d_in, const int* in_sizes, int n_in,
                              void* d_out, int out_size) {
    const float* x  = (const float*)d_in[0];
    const int*   q  = (const int*)d_in[1];
    const float* ws = (const float*)d_in[2];
    const float* lA = (const float*)d_in[3];
    const float* lB = (const float*)d_in[4];
    float* out = (float*)d_out;

    __half* wh = nullptr;
    __half* xh = nullptr;
    cudaGetSymbolAddress((void**)&wh, g_wh);
    cudaGetSymbolAddress((void**)&xh, g_xh);

    convert_x_kernel<<<2048, 256>>>((const float4*)x, (uint2*)xh,
                                    (int)((size_t)M_TOT * D_IN / 4));
    dim3 pgrid(D_IN / 64, D_OUT / 64);
    prep_weff_kernel<<<pgrid, 256>>>(q, ws, lA, lB, (uint2*)wh);

    cudaFuncSetAttribute(gemm_f16_kernel,
                         cudaFuncAttributeMaxDynamicSharedMemorySize, SMEM_BYTES);
    gemm_f16_kernel<<<M_TILES * N_TILES, 256, SMEM_BYTES>>>(xh, wh, out);
}

// round 4
// speedup vs baseline: 2.1611x; 1.1418x over previous
#include <cuda_runtime.h>
#include <cuda_fp16.h>
#include <cstdint>

// ---------------------------------------------------------------------------
// Problem constants
// ---------------------------------------------------------------------------
#define D_IN   4096
#define D_OUT  4096
#define M_TOT  8192
#define RANK   64

// GEMM tiling (fp16 operands, fp32 accumulate)
#define TM 128
#define TN 256
#define TK 64                        // halves per K-stage = 128 bytes
#define STAGES 3
#define K_ITERS (D_IN / TK)          // 64
#define M_TILES (M_TOT / TM)         // 64
#define N_TILES (D_OUT / TN)         // 16

#define PADH 8
#define ROWH (TK + PADH)             // 72 halves = 144 B rows
#define A_STAGE_H (TM * ROWH)        // 9216 halves
#define B_STAGE_H (TN * ROWH)        // 18432 halves
#define SMEM_BYTES ((STAGES * (A_STAGE_H + B_STAGE_H)) * 2)   // 165888

// ---------------------------------------------------------------------------
// Device globals (allocation-free scratch)
// ---------------------------------------------------------------------------
__constant__ float c_nf4[16] = {
    -1.0f, -0.6962f, -0.5251f, -0.3949f, -0.2844f, -0.1848f,
    -0.0911f, 0.0f, 0.0796f, 0.1609f, 0.2461f, 0.3379f,
    0.4407f, 0.5626f, 0.723f, 1.0f};

__device__ __align__(1024) __half g_wh[(size_t)D_OUT * D_IN];  // dequant + folded LoRA
__device__ __align__(1024) __half g_xh[(size_t)M_TOT * D_IN];  // x in fp16

// ---------------------------------------------------------------------------
// Helpers
// ---------------------------------------------------------------------------
__device__ __forceinline__ void cp_async16(uint32_t smem_addr, const void* gptr) {
    asm volatile("cp.async.cg.shared.global [%0], [%1], 16;"
                 :: "r"(smem_addr), "l"(gptr) : "memory");
}
#define CP_COMMIT() asm volatile("cp.async.commit_group;" ::: "memory")
#define CP_WAIT(n)  asm volatile("cp.async.wait_group %0;" :: "n"(n) : "memory")

#define LDMATRIX_X4(r0, r1, r2, r3, addr)                                     \
    asm volatile("ldmatrix.sync.aligned.m8n8.x4.shared.b16 {%0,%1,%2,%3}, [%4];" \
                 : "=r"(r0), "=r"(r1), "=r"(r2), "=r"(r3) : "r"(addr))

__device__ __forceinline__ void mma_f16(float* c, const uint32_t* a,
                                        uint32_t b0, uint32_t b1) {
    asm volatile(
        "mma.sync.aligned.m16n8k16.row.col.f32.f16.f16.f32 "
        "{%0,%1,%2,%3}, {%4,%5,%6,%7}, {%8,%9}, {%0,%1,%2,%3};"
        : "+f"(c[0]), "+f"(c[1]), "+f"(c[2]), "+f"(c[3])
        : "r"(a[0]), "r"(a[1]), "r"(a[2]), "r"(a[3]), "r"(b0), "r"(b1));
}

__device__ __forceinline__ uint32_t h2_bits(__half2 h) {
    return *reinterpret_cast<uint32_t*>(&h);
}

// ---------------------------------------------------------------------------
// Prep 1: convert x to fp16
// ---------------------------------------------------------------------------
__global__ __launch_bounds__(256) void convert_x_kernel(const float4* __restrict__ x,
                                                        uint2* __restrict__ xh, int n4) {
    int i = blockIdx.x * blockDim.x + threadIdx.x;
    int stride = gridDim.x * blockDim.x;
    for (; i < n4; i += stride) {
        float4 v = x[i];
        uint2 o;
        o.x = h2_bits(__floats2half2_rn(v.x, v.y));
        o.y = h2_bits(__floats2half2_rn(v.z, v.w));
        xh[i] = o;
    }
}

// ---------------------------------------------------------------------------
// Prep 2: W_eff[o,i] = NF4[q[o,i]]*scale + 0.25 * (B@A)[o,i], to fp16
// ---------------------------------------------------------------------------
__global__ __launch_bounds__(256) void prep_weff_kernel(
    const int* __restrict__ q, const float* __restrict__ wscale,
    const float* __restrict__ lA, const float* __restrict__ lB,
    uint2* __restrict__ wh) {
    __shared__ float sA[64][68];
    __shared__ float sB[64][68];
    const int tid = threadIdx.x;
    const int i0 = blockIdx.x * 64;
    const int o0 = blockIdx.y * 64;

    for (int idx = tid; idx < 64 * 64; idx += 256) {
        int r = idx >> 6, c = idx & 63;
        sA[r][c] = lA[r * D_IN + i0 + c];
    }
    for (int idx = tid; idx < 64 * 64; idx += 256) {
        int o = idx >> 6, r = idx & 63;
        sB[r][o] = lB[(size_t)(o0 + o) * RANK + r];
    }
    __syncthreads();

    const int tx = tid & 15;
    const int ty = tid >> 4;
    float acc[4][4] = {};
#pragma unroll
    for (int r = 0; r < 64; r++) {
        const float4 av = *reinterpret_cast<const float4*>(&sA[r][tx * 4]);
        const float4 bv = *reinterpret_cast<const float4*>(&sB[r][ty * 4]);
        const float a[4] = {av.x, av.y, av.z, av.w};
        const float b[4] = {bv.x, bv.y, bv.z, bv.w};
#pragma unroll
        for (int ii = 0; ii < 4; ii++)
#pragma unroll
            for (int jj = 0; jj < 4; jj++)
                acc[ii][jj] += b[ii] * a[jj];
    }

    const float s = wscale[0];
#pragma unroll
    for (int ii = 0; ii < 4; ii++) {
        const size_t o = o0 + ty * 4 + ii;
        const int4 qv = *reinterpret_cast<const int4*>(&q[o * D_IN + i0 + tx * 4]);
        float f0 = c_nf4[qv.x & 15] * s + 0.25f * acc[ii][0];
        float f1 = c_nf4[qv.y & 15] * s + 0.25f * acc[ii][1];
        float f2 = c_nf4[qv.z & 15] * s + 0.25f * acc[ii][2];
        float f3 = c_nf4[qv.w & 15] * s + 0.25f * acc[ii][3];
        uint2 o2;
        o2.x = h2_bits(__floats2half2_rn(f0, f1));
        o2.y = h2_bits(__floats2half2_rn(f2, f3));
        wh[(o * D_IN + i0 + tx * 4) >> 2] = o2;
    }
}

// ---------------------------------------------------------------------------
// Main GEMM: C[m,n] = sum_k Xh[m,k] * Wh[n,k]
// 128x256 CTA tile, 64x64 warp tiles (2x4 warps), single-barrier 3-stage loop
// ---------------------------------------------------------------------------
__global__ void __launch_bounds__(256, 1)
gemm_f16_kernel(const __half* __restrict__ A, const __half* __restrict__ B,
                float* __restrict__ C) {
    extern __shared__ __half smem[];
    __half* As = smem;                            // [STAGES][TM][ROWH]
    __half* Bs = smem + STAGES * A_STAGE_H;       // [STAGES][TN][ROWH]

    const int tid = threadIdx.x;
    const int warp = tid >> 5;
    const int lane = tid & 31;

    // tile mapping with M-grouping for L2 reuse
    const int bid = blockIdx.x;
    const int GROUP_M = 8;
    const int per_group = GROUP_M * N_TILES;
    const int g = bid / per_group, rem = bid % per_group;
    const int mt = g * GROUP_M + (rem % GROUP_M);
    const int nt = rem / GROUP_M;
    const int m0 = mt * TM, n0 = nt * TN;

    // warp tile 64x64: 2 (M) x 4 (N)
    const int wm = (warp & 1) * 64;
    const int wn = (warp >> 1) * 64;

    // cp.async indexing: 8 threads per 128B row
    const int lrow = tid >> 3;                    // 0..31
    const int lcolh = (tid & 7) * 8;              // half col 0..56

    const uint32_t as_base = (uint32_t)__cvta_generic_to_shared(As);
    const uint32_t bs_base = (uint32_t)__cvta_generic_to_shared(Bs);

    auto load_stage = [&](int kt, int s) {
        const int k0 = kt * TK;
        const __half* ga = A + (size_t)m0 * D_IN + k0 + lcolh;
        const __half* gb = B + (size_t)n0 * D_IN + k0 + lcolh;
        uint32_t sa = as_base + (s * A_STAGE_H + lcolh) * 2;
        uint32_t sb = bs_base + (s * B_STAGE_H + lcolh) * 2;
#pragma unroll
        for (int it = 0; it < 4; it++) {            // 128 A rows
            int row = lrow + it * 32;
            cp_async16(sa + row * (ROWH * 2), ga + (size_t)row * D_IN);
        }
#pragma unroll
        for (int it = 0; it < 8; it++) {            // 256 B rows
            int row = lrow + it * 32;
            cp_async16(sb + row * (ROWH * 2), gb + (size_t)row * D_IN);
        }
    };

    // prologue: stages 0..STAGES-2
#pragma unroll
    for (int s = 0; s < STAGES - 1; s++) {
        load_stage(s, s);
        CP_COMMIT();
    }

    float acc[4][8][4];
#pragma unroll
    for (int mi = 0; mi < 4; mi++)
#pragma unroll
        for (int ni = 0; ni < 8; ni++)
#pragma unroll
            for (int c = 0; c < 4; c++) acc[mi][ni][c] = 0.f;

    // ldmatrix per-lane addressing
    const int lg = lane >> 3;
    const int lr = lane & 7;
    const int a_row = lr + (lg & 1) * 8;
    const int a_kof = (lg >> 1) * 8;
    const int b_row = lr + (lg >> 1) * 8;
    const int b_kof = (lg & 1) * 8;

    for (int kt = 0; kt < K_ITERS; kt++) {
        CP_WAIT(STAGES - 2);      // stage kt has arrived
        __syncthreads();          // all warps done with slot being overwritten below

        if (kt + STAGES - 1 < K_ITERS)
            load_stage(kt + STAGES - 1, (kt + STAGES - 1) % STAGES);
        CP_COMMIT();

        const int s = kt % STAGES;
        const uint32_t as_st = as_base + (s * A_STAGE_H) * 2;
        const uint32_t bs_st = bs_base + (s * B_STAGE_H) * 2;

#pragma unroll
        for (int kk = 0; kk < 4; kk++) {
            const int k0 = kk * 16;
            uint32_t af[4][4];
#pragma unroll
            for (int mi = 0; mi < 4; mi++) {
                uint32_t addr = as_st + ((wm + mi * 16 + a_row) * ROWH + k0 + a_kof) * 2;
                LDMATRIX_X4(af[mi][0], af[mi][1], af[mi][2], af[mi][3], addr);
            }
            uint32_t bf[4][4];
#pragma unroll
            for (int nj = 0; nj < 4; nj++) {
                uint32_t addr = bs_st + ((wn + nj * 16 + b_row) * ROWH + k0 + b_kof) * 2;
                LDMATRIX_X4(bf[nj][0], bf[nj][1], bf[nj][2], bf[nj][3], addr);
            }
#pragma unroll
            for (int mi = 0; mi < 4; mi++)
#pragma unroll
                for (int nj = 0; nj < 4; nj++) {
                    mma_f16(acc[mi][nj * 2 + 0], af[mi], bf[nj][0], bf[nj][1]);
                    mma_f16(acc[mi][nj * 2 + 1], af[mi], bf[nj][2], bf[nj][3]);
                }
        }
    }

    // epilogue
    const int crow = lane >> 2;
    const int ccol = (lane & 3) * 2;
#pragma unroll
    for (int mi = 0; mi < 4; mi++) {
#pragma unroll
        for (int ni = 0; ni < 8; ni++) {
            const size_t m = (size_t)m0 + wm + mi * 16 + crow;
            const int n = n0 + wn + ni * 8 + ccol;
            float2 v0 = {acc[mi][ni][0], acc[mi][ni][1]};
            float2 v1 = {acc[mi][ni][2], acc[mi][ni][3]};
            *reinterpret_cast<float2*>(C + m * D_OUT + n) = v0;
            *reinterpret_cast<float2*>(C + (m + 8) * D_OUT + n) = v1;
        }
    }
}

// ---------------------------------------------------------------------------
// Host side
// ---------------------------------------------------------------------------
extern "C" void kernel_launch(void* const* d_in, const int* in_sizes, int n_in,
                              void* d_out, int out_size) {
    const float* x  = (const float*)d_in[0];
    const int*   q  = (const int*)d_in[1];
    const float* ws = (const float*)d_in[2];
    const float* lA = (const float*)d_in[3];
    const float* lB = (const float*)d_in[4];
    float* out = (float*)d_out;

    __half* wh = nullptr;
    __half* xh = nullptr;
    cudaGetSymbolAddress((void**)&wh, g_wh);
    cudaGetSymbolAddress((void**)&xh, g_xh);

    convert_x_kernel<<<2048, 256>>>((const float4*)x, (uint2*)xh,
                                    (int)((size_t)M_TOT * D_IN / 4));
    dim3 pgrid(D_IN / 64, D_OUT / 64);
    prep_weff_kernel<<<pgrid, 256>>>(q, ws, lA, lB, (uint2*)wh);

    cudaFuncSetAttribute(gemm_f16_kernel,
                         cudaFuncAttributeMaxDynamicSharedMemorySize, SMEM_BYTES);
    gemm_f16_kernel<<<M_TILES * N_TILES, 256, SMEM_BYTES>>>(xh, wh, out);
}